// round 16
// baseline (speedup 1.0000x reference)
#include <cuda_runtime.h>
#include <cuda_fp16.h>
#include <math.h>

#define IMG    416
#define N_ANG  320
#define N_DET  416
#define N_SAMP 416
#define PAD    244
#define PW     904                  // IMG + 2*PAD
#define NRAY   (N_ANG * N_DET)      // 133120

#define AGRP   4                    // angles per block
#define NAG    (N_ANG / AGRP)       // 80
#define TD     32                   // detectors per block (416 = 13*32, exact)
#define TS     64                   // samples per chunk
#define NDG    13                   // 416 / 32
#define NSC    7                    // ceil(416/64)
#define WIN    144                  // staged window (span <= ~139.4)
#define WSTR   148                  // word stride; mult of 4; 148 mod 32 = 20
#define SMEM_BYTES (WIN * WSTR * 4) // 85,248 B -> 2 CTAs/SM
#define NBLK_R 520                  // NRAY / 256

// Scratch: packed image, g_padh[i] = half2( v[i], v[i+1 within row] )
__device__ __align__(16) __half2 g_padh[PW * PW];   // ~3.27 MB
__device__ float  g_part[NRAY];                     // per-ray projection sum
__device__ double g_blk[NBLK_R];
__device__ unsigned int g_count;                    // last-block counter (self-resetting)

// ---------------------------------------------------------------------------
// Kernel 1: diff + zero-pad + pack into half2 pixel pairs.
// ---------------------------------------------------------------------------
__device__ __forceinline__ float diffv(const float* in, const float* tgt,
                                       int r, int c) {
    int rr = r - PAD;
    int cc = c - PAD;
    if (rr >= 0 && rr < IMG && cc >= 0 && cc < IMG) {
        int j = rr * IMG + cc;
        return in[j] - tgt[j];
    }
    return 0.0f;
}

__global__ void pad_kernel(const float* __restrict__ in,
                           const float* __restrict__ tgt) {
    int i = blockIdx.x * blockDim.x + threadIdx.x;
    if (i >= PW * PW) return;
    int r = i / PW;
    int c = i - r * PW;
    g_padh[i] = __floats2half2_rn(diffv(in, tgt, r, c), diffv(in, tgt, r, c + 1));
}

// ---------------------------------------------------------------------------
// Kernel 2: SMEM-staged fan-beam projection; 4 angles x 32 dets per block,
// chunk loop inside, block-uniform skip of all-zero chunks, and staged
// loads clipped to the nonzero image rectangle (zeros written directly).
// 512 threads; 2 CTAs/SM. Warp w (0..15): angle = ag*4 + (w & 3),
// det octet = w >> 2 in [0,3]; lane = 8 dets x 4 phases. All rays valid.
// ---------------------------------------------------------------------------
__global__ void __launch_bounds__(512, 2) ray_kernel() {
    extern __shared__ __half2 smh[];

    const int dgrp = blockIdx.x;    // 0..12
    const int ag   = blockIdx.y;    // 0..79
    const int tid  = threadIdx.x;

    const double hd_d   = 208.0 * sqrt(2.0);
    const double gmax_d = asin(hd_d / 1075.0);
    const float  THSTEP = (float)(2.0 * M_PI / 320.0);
    const float  GMAX   = (float)gmax_d;
    const float  DG     = (float)(2.0 * gmax_d / (N_DET - 1));
    const float  T0     = (float)(1075.0 - hd_d);
    const float  DTS    = (float)((2.0 * hd_d) / (N_SAMP - 1));
    const float  CTRP   = (float)((IMG - 1) * 0.5 + PAD);   // 451.5

    // ---- per-block geometry (uniform across threads, registers) ----
    const float g_lo = fmaf((float)(dgrp * TD), DG, -GMAX);
    const float g_hi = fmaf((float)(dgrp * TD + TD - 1), DG, -GMAX);

    float bxa[4], bya[4];
    #pragma unroll
    for (int k = 0; k < AGRP; k++) {
        float th = (float)(ag * AGRP + k) * THSTEP;
        float sth, cth;
        sincosf(th, &sth, &cth);
        bxa[k] = fmaf(1075.0f, cth, CTRP);
        bya[k] = fmaf(1075.0f, sth, CTRP);
    }
    float ckc[4], skc[4];
    #pragma unroll
    for (int e = 0; e < 2; e++) {
        float th = (float)(ag * AGRP + e * (AGRP - 1)) * THSTEP;
        sincosf(th + g_lo, &skc[e * 2 + 0], &ckc[e * 2 + 0]);
        sincosf(th + g_hi, &skc[e * 2 + 1], &ckc[e * 2 + 1]);
    }

    // ---- per-thread ray constants ----
    const int warp   = tid >> 5;
    const int lane   = tid & 31;
    const int ak     = warp & 3;
    const int a      = ag * AGRP + ak;
    const int det    = dgrp * TD + (warp >> 2) * 8 + (lane >> 2);
    const int sphase = lane & 3;

    float ncph, nsph;
    {
        const float theta = (float)a * THSTEP;
        const float gamma = fmaf((float)det, DG, -GMAX);
        float sph, cph;
        sincosf(theta + gamma, &sph, &cph);
        ncph = -cph;
        nsph = -sph;
    }

    float acc = 0.0f;

    #pragma unroll 1
    for (int c = 0; c < NSC; c++) {
        const int s_lo = c * TS;
        const int s_hi = min(s_lo + TS - 1, N_SAMP - 1);
        const float t_lo = fmaf((float)s_lo, DTS, T0);
        const float t_hi = fmaf((float)s_hi, DTS, T0);

        float xmin = 1e30f, ymin = 1e30f;
        float xmax = -1e30f, ymax = -1e30f;
        #pragma unroll
        for (int e = 0; e < 2; e++) {
            const float bxe = bxa[e * (AGRP - 1)];
            const float bye = bya[e * (AGRP - 1)];
            #pragma unroll
            for (int j = 0; j < 2; j++) {
                float cc = ckc[e * 2 + j], ss = skc[e * 2 + j];
                float x0 = fmaf(-t_lo, cc, bxe);
                float x1 = fmaf(-t_hi, cc, bxe);
                float y0 = fmaf(-t_lo, ss, bye);
                float y1 = fmaf(-t_hi, ss, bye);
                xmin = fminf(xmin, fminf(x0, x1));
                xmax = fmaxf(xmax, fmaxf(x0, x1));
                ymin = fminf(ymin, fminf(y0, y1));
                ymax = fmaxf(ymax, fmaxf(y0, y1));
            }
        }

        // ---- skip chunks that cannot touch the nonzero image square ----
        if (xmax < (float)(PAD - 3) || xmin > (float)(PAD + IMG + 2) ||
            ymax < (float)(PAD - 3) || ymin > (float)(PAD + IMG + 2))
            continue;   // uniform across block: barriers stay uniform

        const int cmin = (max(0, min((int)floorf(xmin) - 2, PW - WIN))) & ~3;
        const int rmin =  max(0, min((int)floorf(ymin) - 2, PW - WIN));

        __syncthreads();   // previous chunk's reads complete before overwrite

        // ---- stage window; loads clipped to image rect, zeros elsewhere ----
        // half2 word at (row, col) covers pixels (row, col) & (row, col+1):
        //   nonzero iff row in [PAD, PAD+IMG) and col in [PAD-1, PAD+IMG).
        // A uint4 spans 4 words (cols gcol..gcol+3) -> gcol in [PAD-4, PAD+IMG).
        {
            const uint4* __restrict__ src =
                (const uint4*)(g_padh + rmin * PW + cmin);
            uint4* dst = (uint4*)smh;
            const uint4 zero4 = make_uint4(0u, 0u, 0u, 0u);
            for (int rr = warp; rr < WIN; rr += 16) {
                const bool rowin =
                    (unsigned)(rmin + rr - PAD) < (unsigned)IMG;  // warp-uniform
                #pragma unroll
                for (int cc = lane; cc < WIN / 4; cc += 32) {
                    int gcol = cmin + cc * 4;
                    uint4 v = zero4;
                    if (rowin && gcol >= PAD - 4 && gcol < PAD + IMG)
                        v = src[rr * (PW / 4) + cc];
                    dst[rr * (WSTR / 4) + cc] = v;
                }
            }
        }
        __syncthreads();

        // ---- compute 16 samples (identical inner loop to R15) ----
        {
            const float bxl = bxa[ak] - (float)cmin;
            const float byl = bya[ak] - (float)rmin;
            const int s_base = c * TS + sphase;
            const int niter  = (c == NSC - 1) ? 8 : 16;

            #pragma unroll 8
            for (int i = 0; i < niter; i++) {
                float t  = fmaf((float)(s_base + 4 * i), DTS, T0);
                float x  = fmaf(t, ncph, bxl);
                float y  = fmaf(t, nsph, byl);
                float fx = floorf(x);
                float fy = floorf(y);
                float wc = x - fx;
                float wr = y - fy;
                int addr = (int)fy * WSTR + (int)fx;
                float2 tp = __half22float2(smh[addr]);          // (v00, v01)
                float2 bt = __half22float2(smh[addr + WSTR]);   // (v10, v11)
                float top = fmaf(wc, tp.y - tp.x, tp.x);
                float bot = fmaf(wc, bt.y - bt.x, bt.x);
                acc = fmaf(wr, bot - top, acc + top);
            }
        }
    }

    // reduce 4 phases per detector
    acc += __shfl_xor_sync(0xFFFFFFFFu, acc, 1);
    acc += __shfl_xor_sync(0xFFFFFFFFu, acc, 2);

    if (sphase == 0) {
        g_part[a * N_DET + det] = acc;
    }
}

// ---------------------------------------------------------------------------
// Kernel 3: fused epilogue. Each block squares+reduces 256 rays into g_blk;
// the LAST block (atomic counter) deterministically sums g_blk -> out.
// Counter self-resets so graph replays are identical.
// ---------------------------------------------------------------------------
__global__ void raysum_kernel(float* __restrict__ out) {
    __shared__ double smr[256];
    __shared__ bool last;
    const double hd_d = 208.0 * sqrt(2.0);
    const float  DTS  = (float)((2.0 * hd_d) / (N_SAMP - 1));
    int tid = threadIdx.x;
    int ray = blockIdx.x * 256 + tid;

    float val = g_part[ray] * DTS;
    smr[tid] = (double)val * (double)val;
    __syncthreads();
    for (int stride = 128; stride > 0; stride >>= 1) {
        if (tid < stride) smr[tid] += smr[tid + stride];
        __syncthreads();
    }
    if (tid == 0) {
        g_blk[blockIdx.x] = smr[0];
        __threadfence();
        unsigned int t = atomicAdd(&g_count, 1u);
        last = (t == NBLK_R - 1);
    }
    __syncthreads();

    if (last) {
        double s = 0.0;
        for (int i = tid; i < NBLK_R; i += 256)
            s += g_blk[i];
        smr[tid] = s;
        __syncthreads();
        for (int stride = 128; stride > 0; stride >>= 1) {
            if (tid < stride) smr[tid] += smr[tid + stride];
            __syncthreads();
        }
        if (tid == 0) {
            const double SCALE = 512.0 / 416.0 * 0.03;
            out[0] = (float)(smr[0] / (double)NRAY * SCALE);
            g_count = 0;   // reset for next graph replay
        }
    }
}

// ---------------------------------------------------------------------------
extern "C" void kernel_launch(void* const* d_in, const int* in_sizes, int n_in,
                              void* d_out, int out_size) {
    const float* in  = (const float*)d_in[0];
    const float* tgt = (const float*)d_in[1];
    float* out = (float*)d_out;
    (void)in_sizes; (void)n_in; (void)out_size;

    static int configured = 0;
    if (!configured) {
        cudaFuncSetAttribute(ray_kernel,
                             cudaFuncAttributeMaxDynamicSharedMemorySize,
                             SMEM_BYTES);
        configured = 1;
    }

    pad_kernel<<<(PW * PW + 255) / 256, 256>>>(in, tgt);
    ray_kernel<<<dim3(NDG, NAG), 512, SMEM_BYTES>>>();
    raysum_kernel<<<NBLK_R, 256>>>(out);
}

// round 17
// speedup vs baseline: 1.1878x; 1.1878x over previous
#include <cuda_runtime.h>
#include <cuda_fp16.h>
#include <math.h>

#define IMG    416
#define N_ANG  320
#define N_DET  416
#define N_SAMP 416
#define PAD    244
#define PW     904                  // IMG + 2*PAD
#define NRAY   (N_ANG * N_DET)      // 133120

#define AGRP   4                    // angles per block
#define NAG    (N_ANG / AGRP)       // 80
#define TD     32                   // detectors per block (416 = 13*32, exact)
#define TS     64                   // samples per chunk
#define NDG    13                   // 416 / 32
#define NSC    7                    // ceil(416/64)
#define WIN    144                  // staged window (span <= ~139.4)
#define WSTR   148                  // word stride; mult of 4; 148 mod 32 = 20
#define SMEM_BYTES (WIN * WSTR * 4) // 85,248 B -> 2 CTAs/SM
#define NBLK_R 520                  // NRAY / 256

// Scratch: packed image, g_padh[i] = half2( v[i], v[i+1 within row] )
__device__ __align__(16) __half2 g_padh[PW * PW];   // ~3.27 MB
__device__ float  g_part[NRAY];                     // per-ray projection sum
__device__ double g_blk[NBLK_R];
__device__ unsigned int g_count;                    // last-block counter (self-resetting)

// ---------------------------------------------------------------------------
// Kernel 1: diff + zero-pad + pack into half2 pixel pairs.
// ---------------------------------------------------------------------------
__device__ __forceinline__ float diffv(const float* in, const float* tgt,
                                       int r, int c) {
    int rr = r - PAD;
    int cc = c - PAD;
    if (rr >= 0 && rr < IMG && cc >= 0 && cc < IMG) {
        int j = rr * IMG + cc;
        return in[j] - tgt[j];
    }
    return 0.0f;
}

__global__ void pad_kernel(const float* __restrict__ in,
                           const float* __restrict__ tgt) {
    int i = blockIdx.x * blockDim.x + threadIdx.x;
    if (i >= PW * PW) return;
    int r = i / PW;
    int c = i - r * PW;
    g_padh[i] = __floats2half2_rn(diffv(in, tgt, r, c), diffv(in, tgt, r, c + 1));
}

// ---------------------------------------------------------------------------
// Kernel 2: SMEM-staged fan-beam projection; 4 angles x 32 dets per block,
// chunk loop inside, block-uniform skip of all-zero chunks.
// 512 threads; 2 CTAs/SM. Warp w (0..15): angle = ag*4 + (w & 3),
// det octet = w >> 2 in [0,3]; lane = 8 dets x 4 phases. All rays valid.
// (Staging is UNCONDITIONAL — R16's clipped staging regressed.)
// ---------------------------------------------------------------------------
__global__ void __launch_bounds__(512, 2) ray_kernel() {
    extern __shared__ __half2 smh[];

    const int dgrp = blockIdx.x;    // 0..12
    const int ag   = blockIdx.y;    // 0..79
    const int tid  = threadIdx.x;

    const double hd_d   = 208.0 * sqrt(2.0);
    const double gmax_d = asin(hd_d / 1075.0);
    const float  THSTEP = (float)(2.0 * M_PI / 320.0);
    const float  GMAX   = (float)gmax_d;
    const float  DG     = (float)(2.0 * gmax_d / (N_DET - 1));
    const float  T0     = (float)(1075.0 - hd_d);
    const float  DTS    = (float)((2.0 * hd_d) / (N_SAMP - 1));
    const float  CTRP   = (float)((IMG - 1) * 0.5 + PAD);   // 451.5

    // ---- per-block geometry (uniform across threads, registers) ----
    const float g_lo = fmaf((float)(dgrp * TD), DG, -GMAX);
    const float g_hi = fmaf((float)(dgrp * TD + TD - 1), DG, -GMAX);

    float bxa[4], bya[4];
    #pragma unroll
    for (int k = 0; k < AGRP; k++) {
        float th = (float)(ag * AGRP + k) * THSTEP;
        float sth, cth;
        sincosf(th, &sth, &cth);
        bxa[k] = fmaf(1075.0f, cth, CTRP);
        bya[k] = fmaf(1075.0f, sth, CTRP);
    }
    float ckc[4], skc[4];
    #pragma unroll
    for (int e = 0; e < 2; e++) {
        float th = (float)(ag * AGRP + e * (AGRP - 1)) * THSTEP;
        sincosf(th + g_lo, &skc[e * 2 + 0], &ckc[e * 2 + 0]);
        sincosf(th + g_hi, &skc[e * 2 + 1], &ckc[e * 2 + 1]);
    }

    // ---- per-thread ray constants ----
    const int warp   = tid >> 5;
    const int lane   = tid & 31;
    const int ak     = warp & 3;
    const int a      = ag * AGRP + ak;
    const int det    = dgrp * TD + (warp >> 2) * 8 + (lane >> 2);
    const int sphase = lane & 3;

    float ncph, nsph;
    {
        const float theta = (float)a * THSTEP;
        const float gamma = fmaf((float)det, DG, -GMAX);
        float sph, cph;
        sincosf(theta + gamma, &sph, &cph);
        ncph = -cph;
        nsph = -sph;
    }

    float acc = 0.0f;

    #pragma unroll 1
    for (int c = 0; c < NSC; c++) {
        const int s_lo = c * TS;
        const int s_hi = min(s_lo + TS - 1, N_SAMP - 1);
        const float t_lo = fmaf((float)s_lo, DTS, T0);
        const float t_hi = fmaf((float)s_hi, DTS, T0);

        float xmin = 1e30f, ymin = 1e30f;
        float xmax = -1e30f, ymax = -1e30f;
        #pragma unroll
        for (int e = 0; e < 2; e++) {
            const float bxe = bxa[e * (AGRP - 1)];
            const float bye = bya[e * (AGRP - 1)];
            #pragma unroll
            for (int j = 0; j < 2; j++) {
                float cc = ckc[e * 2 + j], ss = skc[e * 2 + j];
                float x0 = fmaf(-t_lo, cc, bxe);
                float x1 = fmaf(-t_hi, cc, bxe);
                float y0 = fmaf(-t_lo, ss, bye);
                float y1 = fmaf(-t_hi, ss, bye);
                xmin = fminf(xmin, fminf(x0, x1));
                xmax = fmaxf(xmax, fmaxf(x0, x1));
                ymin = fminf(ymin, fminf(y0, y1));
                ymax = fmaxf(ymax, fmaxf(y0, y1));
            }
        }

        // ---- skip chunks that cannot touch the nonzero image square ----
        if (xmax < (float)(PAD - 3) || xmin > (float)(PAD + IMG + 2) ||
            ymax < (float)(PAD - 3) || ymin > (float)(PAD + IMG + 2))
            continue;   // uniform across block: barriers stay uniform

        const int cmin = (max(0, min((int)floorf(xmin) - 2, PW - WIN))) & ~3;
        const int rmin =  max(0, min((int)floorf(ymin) - 2, PW - WIN));

        __syncthreads();   // previous chunk's reads complete before overwrite

        // ---- stage WIN x WIN half2 words via uint4; warp-row layout ----
        {
            const uint4* __restrict__ src =
                (const uint4*)(g_padh + rmin * PW + cmin);
            uint4* dst = (uint4*)smh;
            for (int rr = warp; rr < WIN; rr += 16) {
                #pragma unroll
                for (int cc = lane; cc < WIN / 4; cc += 32) {
                    dst[rr * (WSTR / 4) + cc] = src[rr * (PW / 4) + cc];
                }
            }
        }
        __syncthreads();

        // ---- compute 16 samples (identical inner loop to R15) ----
        {
            const float bxl = bxa[ak] - (float)cmin;
            const float byl = bya[ak] - (float)rmin;
            const int s_base = c * TS + sphase;
            const int niter  = (c == NSC - 1) ? 8 : 16;

            #pragma unroll 8
            for (int i = 0; i < niter; i++) {
                float t  = fmaf((float)(s_base + 4 * i), DTS, T0);
                float x  = fmaf(t, ncph, bxl);
                float y  = fmaf(t, nsph, byl);
                float fx = floorf(x);
                float fy = floorf(y);
                float wc = x - fx;
                float wr = y - fy;
                int addr = (int)fy * WSTR + (int)fx;
                float2 tp = __half22float2(smh[addr]);          // (v00, v01)
                float2 bt = __half22float2(smh[addr + WSTR]);   // (v10, v11)
                float top = fmaf(wc, tp.y - tp.x, tp.x);
                float bot = fmaf(wc, bt.y - bt.x, bt.x);
                acc = fmaf(wr, bot - top, acc + top);
            }
        }
    }

    // reduce 4 phases per detector
    acc += __shfl_xor_sync(0xFFFFFFFFu, acc, 1);
    acc += __shfl_xor_sync(0xFFFFFFFFu, acc, 2);

    if (sphase == 0) {
        g_part[a * N_DET + det] = acc;
    }
}

// ---------------------------------------------------------------------------
// Kernel 3: fused epilogue. Each block squares+reduces 256 rays into g_blk;
// the LAST block (atomic counter) deterministically sums g_blk -> out.
// Counter self-resets so graph replays are identical.
// ---------------------------------------------------------------------------
__global__ void raysum_kernel(float* __restrict__ out) {
    __shared__ double smr[256];
    __shared__ bool last;
    const double hd_d = 208.0 * sqrt(2.0);
    const float  DTS  = (float)((2.0 * hd_d) / (N_SAMP - 1));
    int tid = threadIdx.x;
    int ray = blockIdx.x * 256 + tid;

    float val = g_part[ray] * DTS;
    smr[tid] = (double)val * (double)val;
    __syncthreads();
    for (int stride = 128; stride > 0; stride >>= 1) {
        if (tid < stride) smr[tid] += smr[tid + stride];
        __syncthreads();
    }
    if (tid == 0) {
        g_blk[blockIdx.x] = smr[0];
        __threadfence();
        unsigned int t = atomicAdd(&g_count, 1u);
        last = (t == NBLK_R - 1);
    }
    __syncthreads();

    if (last) {
        double s = 0.0;
        for (int i = tid; i < NBLK_R; i += 256)
            s += g_blk[i];
        smr[tid] = s;
        __syncthreads();
        for (int stride = 128; stride > 0; stride >>= 1) {
            if (tid < stride) smr[tid] += smr[tid + stride];
            __syncthreads();
        }
        if (tid == 0) {
            const double SCALE = 512.0 / 416.0 * 0.03;
            out[0] = (float)(smr[0] / (double)NRAY * SCALE);
            g_count = 0;   // reset for next graph replay
        }
    }
}

// ---------------------------------------------------------------------------
extern "C" void kernel_launch(void* const* d_in, const int* in_sizes, int n_in,
                              void* d_out, int out_size) {
    const float* in  = (const float*)d_in[0];
    const float* tgt = (const float*)d_in[1];
    float* out = (float*)d_out;
    (void)in_sizes; (void)n_in; (void)out_size;

    static int configured = 0;
    if (!configured) {
        cudaFuncSetAttribute(ray_kernel,
                             cudaFuncAttributeMaxDynamicSharedMemorySize,
                             SMEM_BYTES);
        configured = 1;
    }

    pad_kernel<<<(PW * PW + 255) / 256, 256>>>(in, tgt);
    ray_kernel<<<dim3(NDG, NAG), 512, SMEM_BYTES>>>();
    raysum_kernel<<<NBLK_R, 256>>>(out);
}